// round 2
// baseline (speedup 1.0000x reference)
#include <cuda_runtime.h>

#define Bb 2
#define Nn 1024
#define Dd 1024
#define Hh 16
#define DhC 64
#define Ss 64
#define DbC 512

// -------- scratch (static device globals; no allocations allowed) --------
__device__ float g_Q[Bb*Nn*Dd];
__device__ float g_K[Bb*Nn*Dd];
__device__ float g_V[Bb*Nn*Dd];
__device__ float g_G[Bb*Nn*Dd];      // sigmoid gate
__device__ float g_std[Bb*Nn*Dd];    // std attention out
__device__ float g_infl[Bb*Nn*Ss];
__device__ float g_total[Bb*Ss];
__device__ float g_gath[Bb*Ss*Dd];
__device__ float g_enc[Bb*Ss*DbC];
__device__ float g_trans[Bb*Ss*DbC];
__device__ float g_dec[Bb*Ss*Dd];
__device__ float g_blend[Bb*Nn*Dd];

// ============================================================
// Generic SGEMM: C[M,N] = A[M,K] @ B[K,N]  (all row-major)
// Requires M%128==0, N%128==0, K%16==0 (true for all call sites).
// epi: 0=none, 1=sigmoid(v+bias[col]), 2=relu(v+bias[col]), 3=v+bias[col]
// ============================================================
__global__ __launch_bounds__(256) void sgemm_kernel(
    const float* __restrict__ A, const float* __restrict__ B,
    const float* __restrict__ bias, float* __restrict__ C,
    int M, int N, int K, int epi)
{
    __shared__ float As[16][128];   // transposed: As[k][m]
    __shared__ float Bs[16][128];

    int tid = threadIdx.x;
    int tx = tid & 15;          // col group
    int ty = tid >> 4;          // row group
    int rowBase = blockIdx.y * 128;
    int colBase = blockIdx.x * 128;

    float acc[8][8];
#pragma unroll
    for (int i = 0; i < 8; i++)
#pragma unroll
        for (int j = 0; j < 8; j++) acc[i][j] = 0.f;

    int aRow0 = tid >> 2;            // 0..63
    int aCol0 = (tid & 3) << 2;      // 0,4,8,12
    int bRow0 = tid >> 5;            // 0..7
    int bCol0 = (tid & 31) << 2;     // 0..124

    for (int k0 = 0; k0 < K; k0 += 16) {
#pragma unroll
        for (int i = 0; i < 2; i++) {
            int r = aRow0 + i * 64;
            float4 a = *(const float4*)&A[(size_t)(rowBase + r) * K + k0 + aCol0];
            As[aCol0 + 0][r] = a.x;
            As[aCol0 + 1][r] = a.y;
            As[aCol0 + 2][r] = a.z;
            As[aCol0 + 3][r] = a.w;
        }
#pragma unroll
        for (int i = 0; i < 2; i++) {
            int r = bRow0 + i * 8;
            *(float4*)&Bs[r][bCol0] = *(const float4*)&B[(size_t)(k0 + r) * N + colBase + bCol0];
        }
        __syncthreads();
#pragma unroll
        for (int kk = 0; kk < 16; kk++) {
            float a[8], b[8];
            *(float4*)&a[0] = *(float4*)&As[kk][ty * 8];
            *(float4*)&a[4] = *(float4*)&As[kk][ty * 8 + 4];
            *(float4*)&b[0] = *(float4*)&Bs[kk][tx * 8];
            *(float4*)&b[4] = *(float4*)&Bs[kk][tx * 8 + 4];
#pragma unroll
            for (int i = 0; i < 8; i++)
#pragma unroll
                for (int j = 0; j < 8; j++)
                    acc[i][j] += a[i] * b[j];
        }
        __syncthreads();
    }

#pragma unroll
    for (int i = 0; i < 8; i++) {
        int row = rowBase + ty * 8 + i;
#pragma unroll
        for (int j = 0; j < 8; j += 4) {
            int col = colBase + tx * 8 + j;
            float4 v;
            float t0 = acc[i][j], t1 = acc[i][j+1], t2 = acc[i][j+2], t3 = acc[i][j+3];
            if (epi == 1) {
                t0 = 1.f / (1.f + expf(-(t0 + bias[col+0])));
                t1 = 1.f / (1.f + expf(-(t1 + bias[col+1])));
                t2 = 1.f / (1.f + expf(-(t2 + bias[col+2])));
                t3 = 1.f / (1.f + expf(-(t3 + bias[col+3])));
            } else if (epi == 2) {
                t0 = fmaxf(t0 + bias[col+0], 0.f);
                t1 = fmaxf(t1 + bias[col+1], 0.f);
                t2 = fmaxf(t2 + bias[col+2], 0.f);
                t3 = fmaxf(t3 + bias[col+3], 0.f);
            } else if (epi == 3) {
                t0 += bias[col+0]; t1 += bias[col+1]; t2 += bias[col+2]; t3 += bias[col+3];
            }
            v.x = t0; v.y = t1; v.z = t2; v.w = t3;
            *(float4*)&C[(size_t)row * N + col] = v;
        }
    }
}

// ============================================================
// Flash attention: one block = (q-tile of 64, b*H+h). 256 threads.
// Exactly 48KB static smem (3 x 64x64 f32). K stored transposed in smem.
// ============================================================
__device__ __forceinline__ float redmax16(float v) {
    v = fmaxf(v, __shfl_xor_sync(0xffffffffu, v, 8, 16));
    v = fmaxf(v, __shfl_xor_sync(0xffffffffu, v, 4, 16));
    v = fmaxf(v, __shfl_xor_sync(0xffffffffu, v, 2, 16));
    v = fmaxf(v, __shfl_xor_sync(0xffffffffu, v, 1, 16));
    return v;
}
__device__ __forceinline__ float redsum16(float v) {
    v += __shfl_xor_sync(0xffffffffu, v, 8, 16);
    v += __shfl_xor_sync(0xffffffffu, v, 4, 16);
    v += __shfl_xor_sync(0xffffffffu, v, 2, 16);
    v += __shfl_xor_sync(0xffffffffu, v, 1, 16);
    return v;
}

__global__ __launch_bounds__(256) void attn_kernel(
    const float* __restrict__ Q, const float* __restrict__ K,
    const float* __restrict__ V, float* __restrict__ O)
{
    __shared__ float Qs[64][64];
    __shared__ float KP[64][64];   // K transposed (KP[d][j]) then reused as P[i][j]
    __shared__ float Vs[64][64];

    int tid = threadIdx.x;
    int tx = tid & 15, ty = tid >> 4;
    int qb = blockIdx.x * 64;
    int b = blockIdx.y >> 4, h = blockIdx.y & 15;

    const float* Qb = Q + (size_t)b * Nn * Dd + h * DhC;
    const float* Kb = K + (size_t)b * Nn * Dd + h * DhC;
    const float* Vb = V + (size_t)b * Nn * Dd + h * DhC;

#pragma unroll
    for (int i = 0; i < 4; i++) {
        int e = tid + i * 256;
        int r = e >> 4, c = (e & 15) << 2;
        *(float4*)&Qs[r][c] = *(const float4*)&Qb[(size_t)(qb + r) * Dd + c];
    }

    float m[4], l[4], o[4][4];
#pragma unroll
    for (int i = 0; i < 4; i++) {
        m[i] = -1e30f; l[i] = 0.f;
#pragma unroll
        for (int j = 0; j < 4; j++) o[i][j] = 0.f;
    }

    for (int kt = 0; kt < 16; kt++) {
        __syncthreads();   // previous iteration's KP/Vs reads done (also covers Qs fill)
#pragma unroll
        for (int i = 0; i < 4; i++) {
            int e = tid + i * 256;
            int r = e >> 4, c = (e & 15) << 2;
            float4 kv = *(const float4*)&Kb[(size_t)(kt * 64 + r) * Dd + c];
            KP[c + 0][r] = kv.x; KP[c + 1][r] = kv.y;
            KP[c + 2][r] = kv.z; KP[c + 3][r] = kv.w;
            *(float4*)&Vs[r][c] = *(const float4*)&Vb[(size_t)(kt * 64 + r) * Dd + c];
        }
        __syncthreads();

        float s[4][4];
#pragma unroll
        for (int i = 0; i < 4; i++)
#pragma unroll
            for (int j = 0; j < 4; j++) s[i][j] = 0.f;

#pragma unroll 4
        for (int d = 0; d < 64; d++) {
            float4 k4 = *(float4*)&KP[d][tx << 2];
            float q0 = Qs[(ty << 2) + 0][d];
            float q1 = Qs[(ty << 2) + 1][d];
            float q2 = Qs[(ty << 2) + 2][d];
            float q3 = Qs[(ty << 2) + 3][d];
            s[0][0] += q0 * k4.x; s[0][1] += q0 * k4.y; s[0][2] += q0 * k4.z; s[0][3] += q0 * k4.w;
            s[1][0] += q1 * k4.x; s[1][1] += q1 * k4.y; s[1][2] += q1 * k4.z; s[1][3] += q1 * k4.w;
            s[2][0] += q2 * k4.x; s[2][1] += q2 * k4.y; s[2][2] += q2 * k4.z; s[2][3] += q2 * k4.w;
            s[3][0] += q3 * k4.x; s[3][1] += q3 * k4.y; s[3][2] += q3 * k4.z; s[3][3] += q3 * k4.w;
        }

        const float scale = 0.125f;   // Dh^-0.5
#pragma unroll
        for (int i = 0; i < 4; i++) {
#pragma unroll
            for (int j = 0; j < 4; j++) s[i][j] *= scale;
            float tm = fmaxf(fmaxf(s[i][0], s[i][1]), fmaxf(s[i][2], s[i][3]));
            tm = redmax16(tm);
            float mn = fmaxf(m[i], tm);
            float alpha = __expf(m[i] - mn);
            float rs = 0.f;
#pragma unroll
            for (int j = 0; j < 4; j++) { s[i][j] = __expf(s[i][j] - mn); rs += s[i][j]; }
            rs = redsum16(rs);
            l[i] = l[i] * alpha + rs;
            m[i] = mn;
#pragma unroll
            for (int j = 0; j < 4; j++) o[i][j] *= alpha;
        }

        __syncthreads();  // all KP(K-transposed) reads done before overwrite with P
#pragma unroll
        for (int i = 0; i < 4; i++) {
            float4 p4; p4.x = s[i][0]; p4.y = s[i][1]; p4.z = s[i][2]; p4.w = s[i][3];
            *(float4*)&KP[(ty << 2) + i][tx << 2] = p4;
        }
        __syncthreads();

#pragma unroll 4
        for (int j = 0; j < 64; j++) {
            float4 v4 = *(float4*)&Vs[j][tx << 2];
            float p0 = KP[(ty << 2) + 0][j];
            float p1 = KP[(ty << 2) + 1][j];
            float p2 = KP[(ty << 2) + 2][j];
            float p3 = KP[(ty << 2) + 3][j];
            o[0][0] += p0 * v4.x; o[0][1] += p0 * v4.y; o[0][2] += p0 * v4.z; o[0][3] += p0 * v4.w;
            o[1][0] += p1 * v4.x; o[1][1] += p1 * v4.y; o[1][2] += p1 * v4.z; o[1][3] += p1 * v4.w;
            o[2][0] += p2 * v4.x; o[2][1] += p2 * v4.y; o[2][2] += p2 * v4.z; o[2][3] += p2 * v4.w;
            o[3][0] += p3 * v4.x; o[3][1] += p3 * v4.y; o[3][2] += p3 * v4.z; o[3][3] += p3 * v4.w;
        }
    }

#pragma unroll
    for (int i = 0; i < 4; i++) {
        float inv = 1.f / l[i];
        float4 r;
        r.x = o[i][0] * inv; r.y = o[i][1] * inv; r.z = o[i][2] * inv; r.w = o[i][3] * inv;
        *(float4*)&O[(size_t)(b * Nn + qb + (ty << 2) + i) * Dd + h * DhC + (tx << 2)] = r;
    }
}

// ============================================================
// Splat influence: infl[b,n,s] = exp(-0.5*max(|x|^2+|sp|^2-2 x.sp,0)/sc^2)*|imp|
// grid (N, B), 256 threads. One warp per splat (8 splats/pass).
// ============================================================
__global__ __launch_bounds__(256) void infl_kernel(
    const float* __restrict__ x, const float* __restrict__ sp,
    const float* __restrict__ sscale, const float* __restrict__ simp,
    float* __restrict__ infl)
{
    __shared__ float xs[Dd];
    __shared__ float red[8];
    int n = blockIdx.x, b = blockIdx.y;
    int tid = threadIdx.x;
    int lane = tid & 31, w = tid >> 5;
    const float* xr = &x[(size_t)(b * Nn + n) * Dd];

    float p2 = 0.f;
    for (int i = tid; i < Dd; i += 256) { float v = xr[i]; xs[i] = v; p2 += v * v; }
#pragma unroll
    for (int off = 16; off; off >>= 1) p2 += __shfl_xor_sync(0xffffffffu, p2, off);
    if (lane == 0) red[w] = p2;
    __syncthreads();
    float x2 = 0.f;
#pragma unroll
    for (int i = 0; i < 8; i++) x2 += red[i];

    for (int s = w; s < Ss; s += 8) {
        const float* spr = &sp[(size_t)s * Dd];
        float dot = 0.f, s2 = 0.f;
        for (int d = lane; d < Dd; d += 32) {
            float pv = spr[d];
            dot += xs[d] * pv;
            s2 += pv * pv;
        }
#pragma unroll
        for (int off = 16; off; off >>= 1) {
            dot += __shfl_xor_sync(0xffffffffu, dot, off);
            s2  += __shfl_xor_sync(0xffffffffu, s2, off);
        }
        if (lane == 0) {
            float d2 = fmaxf(x2 + s2 - 2.f * dot, 0.f);
            float sc = fmaxf(fabsf(sscale[s]), 1e-6f);
            infl[(size_t)(b * Nn + n) * Ss + s] = expf(-0.5f * d2 / (sc * sc)) * fabsf(simp[s]);
        }
    }
}

// total[b,s] = max(sum_n infl, 1e-8).  grid (S, B), 256 threads.
__global__ __launch_bounds__(256) void total_kernel(
    const float* __restrict__ infl, float* __restrict__ total)
{
    __shared__ float red[8];
    int s = blockIdx.x, b = blockIdx.y, tid = threadIdx.x;
    float acc = 0.f;
    for (int n = tid; n < Nn; n += 256) acc += infl[(size_t)(b * Nn + n) * Ss + s];
#pragma unroll
    for (int off = 16; off; off >>= 1) acc += __shfl_xor_sync(0xffffffffu, acc, off);
    if ((tid & 31) == 0) red[tid >> 5] = acc;
    __syncthreads();
    if (tid == 0) {
        float t = 0.f;
#pragma unroll
        for (int i = 0; i < 8; i++) t += red[i];
        total[b * Ss + s] = fmaxf(t, 1e-8f);
    }
}

// gathered[b,s,:] = (sum_n infl[b,n,s] * x[b,n,:]) / total[b,s]. grid (S,B), 256 thr.
__global__ __launch_bounds__(256) void gather_kernel(
    const float* __restrict__ x, const float* __restrict__ infl,
    const float* __restrict__ total, float* __restrict__ gath)
{
    int s = blockIdx.x, b = blockIdx.y, tid = threadIdx.x;
    float acc[4] = {0.f, 0.f, 0.f, 0.f};
    for (int n = 0; n < Nn; n++) {
        float wv = __ldg(&infl[(size_t)(b * Nn + n) * Ss + s]);
        if (wv != 0.f) {   // exact semantics (adding 0*x contributes exactly 0)
            const float* xr = &x[(size_t)(b * Nn + n) * Dd];
#pragma unroll
            for (int i = 0; i < 4; i++) acc[i] += wv * xr[tid + 256 * i];
        }
    }
    float inv = 1.f / total[b * Ss + s];
#pragma unroll
    for (int i = 0; i < 4; i++)
        gath[(size_t)(b * Ss + s) * Dd + tid + 256 * i] = acc[i] * inv;
}

// trans[b,s,e] = enc[b,s,:] @ Wt[s,:,e] + bt[s,e].  grid (S, Db/128), 128 thr.
__global__ __launch_bounds__(128) void trans_kernel(
    const float* __restrict__ enc, const float* __restrict__ Wt,
    const float* __restrict__ bt, float* __restrict__ trans)
{
    int s = blockIdx.x;
    int e = blockIdx.y * 128 + threadIdx.x;
    const float* wp = &Wt[(size_t)s * DbC * DbC];
    const float* e0 = &enc[(size_t)(0 * Ss + s) * DbC];
    const float* e1 = &enc[(size_t)(1 * Ss + s) * DbC];
    float a0 = 0.f, a1 = 0.f;
    for (int d = 0; d < DbC; d++) {
        float wv = wp[(size_t)d * DbC + e];
        a0 += e0[d] * wv;
        a1 += e1[d] * wv;
    }
    float bv = bt[s * DbC + e];
    trans[(size_t)(0 * Ss + s) * DbC + e] = a0 + bv;
    trans[(size_t)(1 * Ss + s) * DbC + e] = a1 + bv;
}

// blend = 0.6*std_out + 0.4*(infl@dec)*gate.  grid (N, B), 256 thr.
__global__ __launch_bounds__(256) void flow_blend_kernel(
    const float* __restrict__ infl, const float* __restrict__ dec,
    const float* __restrict__ gate, const float* __restrict__ stdo,
    float* __restrict__ blend)
{
    __shared__ float is[Ss];
    int n = blockIdx.x, b = blockIdx.y, tid = threadIdx.x;
    if (tid < Ss) is[tid] = infl[(size_t)(b * Nn + n) * Ss + tid];
    __syncthreads();
#pragma unroll
    for (int i = 0; i < 4; i++) {
        int d = tid + i * 256;
        float acc = 0.f;
#pragma unroll 8
        for (int s = 0; s < Ss; s++)
            acc += is[s] * dec[(size_t)(b * Ss + s) * Dd + d];
        size_t idx = (size_t)(b * Nn + n) * Dd + d;
        blend[idx] = 0.6f * stdo[idx] + 0.4f * acc * gate[idx];
    }
}

// ============================================================
extern "C" void kernel_launch(void* const* d_in, const int* in_sizes, int n_in,
                              void* d_out, int out_size)
{
    const float* x    = (const float*)d_in[0];
    const float* Wq   = (const float*)d_in[1];
    const float* Wk   = (const float*)d_in[2];
    const float* Wv   = (const float*)d_in[3];
    const float* Wo   = (const float*)d_in[4];
    const float* sp   = (const float*)d_in[5];
    const float* ssc  = (const float*)d_in[6];
    const float* simp = (const float*)d_in[7];
    const float* We   = (const float*)d_in[8];
    const float* be   = (const float*)d_in[9];
    const float* Wt   = (const float*)d_in[10];
    const float* bt   = (const float*)d_in[11];
    const float* Wd   = (const float*)d_in[12];
    const float* bd   = (const float*)d_in[13];
    const float* Wg   = (const float*)d_in[14];
    const float* bg   = (const float*)d_in[15];

    float *Qp, *Kp, *Vp, *Gp, *Stdp, *Inflp, *Totp, *Gathp, *Encp, *Transp, *Decp, *Blendp;
    cudaGetSymbolAddress((void**)&Qp, g_Q);
    cudaGetSymbolAddress((void**)&Kp, g_K);
    cudaGetSymbolAddress((void**)&Vp, g_V);
    cudaGetSymbolAddress((void**)&Gp, g_G);
    cudaGetSymbolAddress((void**)&Stdp, g_std);
    cudaGetSymbolAddress((void**)&Inflp, g_infl);
    cudaGetSymbolAddress((void**)&Totp, g_total);
    cudaGetSymbolAddress((void**)&Gathp, g_gath);
    cudaGetSymbolAddress((void**)&Encp, g_enc);
    cudaGetSymbolAddress((void**)&Transp, g_trans);
    cudaGetSymbolAddress((void**)&Decp, g_dec);
    cudaGetSymbolAddress((void**)&Blendp, g_blend);

    const int M = Bb * Nn;   // 2048

    // QKV + gate projections
    sgemm_kernel<<<dim3(Dd / 128, M / 128), 256>>>(x, Wq, nullptr, Qp, M, Dd, Dd, 0);
    sgemm_kernel<<<dim3(Dd / 128, M / 128), 256>>>(x, Wk, nullptr, Kp, M, Dd, Dd, 0);
    sgemm_kernel<<<dim3(Dd / 128, M / 128), 256>>>(x, Wv, nullptr, Vp, M, Dd, Dd, 0);
    sgemm_kernel<<<dim3(Dd / 128, M / 128), 256>>>(x, Wg, bg, Gp, M, Dd, Dd, 1);

    // standard attention
    attn_kernel<<<dim3(Nn / 64, Bb * Hh), 256>>>(Qp, Kp, Vp, Stdp);

    // splat pipeline
    infl_kernel<<<dim3(Nn, Bb), 256>>>(x, sp, ssc, simp, Inflp);
    total_kernel<<<dim3(Ss, Bb), 256>>>(Inflp, Totp);
    gather_kernel<<<dim3(Ss, Bb), 256>>>(x, Inflp, Totp, Gathp);
    sgemm_kernel<<<dim3(DbC / 128, (Bb * Ss) / 128), 256>>>(Gathp, We, be, Encp, Bb * Ss, DbC, Dd, 2);
    trans_kernel<<<dim3(Ss, DbC / 128), 128>>>(Encp, Wt, bt, Transp);
    sgemm_kernel<<<dim3(Dd / 128, (Bb * Ss) / 128), 256>>>(Transp, Wd, bd, Decp, Bb * Ss, Dd, DbC, 3);
    flow_blend_kernel<<<dim3(Nn, Bb), 256>>>(Inflp, Decp, Gp, Stdp, Blendp);

    // final projection
    sgemm_kernel<<<dim3(Dd / 128, M / 128), 256>>>(Blendp, Wo, nullptr, (float*)d_out, M, Dd, Dd, 0);
}

// round 3
// speedup vs baseline: 1.2726x; 1.2726x over previous
#include <cuda_runtime.h>
#include <cstdint>

#define Bb 2
#define Nn 1024
#define Dd 1024
#define Hh 16
#define DhC 64
#define Ss 64
#define DbC 512

// -------- scratch (static device globals; no allocations allowed) --------
__device__ float g_Q[Bb*Nn*Dd];
__device__ float g_K[Bb*Nn*Dd];
__device__ float g_V[Bb*Nn*Dd];
__device__ float g_G[Bb*Nn*Dd];      // sigmoid gate
__device__ float g_std[Bb*Nn*Dd];    // std attention out
__device__ float g_infl[Bb*Nn*Ss];
__device__ float g_total[Bb*Ss];
__device__ float g_gath[Bb*Ss*Dd];
__device__ float g_enc[Bb*Ss*DbC];
__device__ float g_trans[Bb*Ss*DbC];
__device__ float g_dec[Bb*Ss*Dd];
__device__ float g_blend[Bb*Nn*Dd];

// ============================================================
// TF32 tensor-core GEMM with 3-pass split (fp32-class accuracy).
// C[M, segN] = A[M,K] @ B[K,segN] per segment; the fused QKVG GEMM
// uses 4 segments of 1024 columns each (block-uniform segment).
// BM=128, BN=128, BK=16, 256 threads = 8 warps (2x4), warp tile 64x32.
// epi: 0=none, 1=sigmoid(v+bias), 2=relu(v+bias), 3=v+bias
// ============================================================
struct GArgs {
    const float* A;
    const float* B[4];
    const float* bias[4];
    float*       C[4];
    int K;
    int segN;
    int epi[4];
};

__device__ __forceinline__ uint32_t f2tf32(float x) {
    uint32_t r;
    asm("cvt.rna.tf32.f32 %0, %1;" : "=r"(r) : "f"(x));
    return r;
}

__device__ __forceinline__ void mma_tf32(float* c,
    uint32_t a0, uint32_t a1, uint32_t a2, uint32_t a3,
    uint32_t b0, uint32_t b1)
{
    asm volatile(
        "mma.sync.aligned.m16n8k8.row.col.f32.tf32.tf32.f32 "
        "{%0,%1,%2,%3},{%4,%5,%6,%7},{%8,%9},{%0,%1,%2,%3};"
        : "+f"(c[0]), "+f"(c[1]), "+f"(c[2]), "+f"(c[3])
        : "r"(a0), "r"(a1), "r"(a2), "r"(a3), "r"(b0), "r"(b1));
}

#define SPAD 140   // smem row stride: frag LDS conflict-free (8k+m style bank spread)

__global__ __launch_bounds__(256, 2) void tf32_gemm(GArgs g)
{
    __shared__ float As[16][SPAD];   // As[k][m]
    __shared__ float Bs[16][SPAD];   // Bs[k][n]

    const int tid = threadIdx.x;
    const int warp = tid >> 5;
    const int lane = tid & 31;
    const int lr = lane >> 2;      // 0..7
    const int lc = lane & 3;       // 0..3
    const int wm = warp >> 2;      // 0..1  (64-row slab)
    const int wn = warp & 3;       // 0..3  (32-col slab)

    const int seg    = (blockIdx.x * 128) / g.segN;
    const int colSeg = (blockIdx.x * 128) % g.segN;
    const int rowBase = blockIdx.y * 128;
    const float* __restrict__ Bp   = g.B[seg];
    const float* __restrict__ bias = g.bias[seg];
    float* __restrict__ Cp         = g.C[seg];
    const int epi  = g.epi[seg];
    const int K    = g.K;
    const int segN = g.segN;

    const int aRow0 = tid >> 2;          // 0..63
    const int aCol0 = (tid & 3) << 2;    // 0,4,8,12
    const int bRow0 = tid >> 5;          // 0..7
    const int bCol0 = (tid & 31) << 2;   // 0..124

    float acc[4][4][4];
#pragma unroll
    for (int i = 0; i < 4; i++)
#pragma unroll
        for (int j = 0; j < 4; j++)
#pragma unroll
            for (int q = 0; q < 4; q++) acc[i][j][q] = 0.f;

    const int T = K >> 4;
    float4 sa[2], sb[2];
#pragma unroll
    for (int i = 0; i < 2; i++) {
        sa[i] = *(const float4*)&g.A[(size_t)(rowBase + aRow0 + i * 64) * K + aCol0];
        sb[i] = *(const float4*)&Bp[(size_t)(bRow0 + i * 8) * segN + colSeg + bCol0];
    }

    for (int t = 0; t < T; t++) {
        // stage -> smem (A transposed)
#pragma unroll
        for (int i = 0; i < 2; i++) {
            int r = aRow0 + i * 64;
            As[aCol0 + 0][r] = sa[i].x;
            As[aCol0 + 1][r] = sa[i].y;
            As[aCol0 + 2][r] = sa[i].z;
            As[aCol0 + 3][r] = sa[i].w;
            *(float4*)&Bs[bRow0 + i * 8][bCol0] = sb[i];
        }
        __syncthreads();

        if (t + 1 < T) {
            int k0 = (t + 1) * 16;
#pragma unroll
            for (int i = 0; i < 2; i++) {
                sa[i] = *(const float4*)&g.A[(size_t)(rowBase + aRow0 + i * 64) * K + k0 + aCol0];
                sb[i] = *(const float4*)&Bp[(size_t)(k0 + bRow0 + i * 8) * segN + colSeg + bCol0];
            }
        }

#pragma unroll
        for (int kk = 0; kk < 16; kk += 8) {
            uint32_t bh[4][2], bl[4][2];
#pragma unroll
            for (int nt = 0; nt < 4; nt++) {
                int n0 = wn * 32 + nt * 8 + lr;
                float b0 = Bs[kk + lc][n0];
                float b1 = Bs[kk + 4 + lc][n0];
                bh[nt][0] = f2tf32(b0);
                bl[nt][0] = f2tf32(b0 - __uint_as_float(bh[nt][0]));
                bh[nt][1] = f2tf32(b1);
                bl[nt][1] = f2tf32(b1 - __uint_as_float(bh[nt][1]));
            }
#pragma unroll
            for (int mt = 0; mt < 4; mt++) {
                int m0 = wm * 64 + mt * 16;
                float a0 = As[kk + lc][m0 + lr];
                float a1 = As[kk + lc][m0 + lr + 8];
                float a2 = As[kk + 4 + lc][m0 + lr];
                float a3 = As[kk + 4 + lc][m0 + lr + 8];
                uint32_t ah0 = f2tf32(a0), ah1 = f2tf32(a1), ah2 = f2tf32(a2), ah3 = f2tf32(a3);
                uint32_t al0 = f2tf32(a0 - __uint_as_float(ah0));
                uint32_t al1 = f2tf32(a1 - __uint_as_float(ah1));
                uint32_t al2 = f2tf32(a2 - __uint_as_float(ah2));
                uint32_t al3 = f2tf32(a3 - __uint_as_float(ah3));
#pragma unroll
                for (int nt = 0; nt < 4; nt++) {
                    mma_tf32(acc[mt][nt], ah0, ah1, ah2, ah3, bh[nt][0], bh[nt][1]);
                    mma_tf32(acc[mt][nt], ah0, ah1, ah2, ah3, bl[nt][0], bl[nt][1]);
                    mma_tf32(acc[mt][nt], al0, al1, al2, al3, bh[nt][0], bh[nt][1]);
                }
            }
        }
        __syncthreads();
    }

    // epilogue
#pragma unroll
    for (int mt = 0; mt < 4; mt++) {
#pragma unroll
        for (int nt = 0; nt < 4; nt++) {
            int col = colSeg + wn * 32 + nt * 8 + 2 * lc;
            float b0 = 0.f, b1 = 0.f;
            if (epi != 0) { b0 = bias[col]; b1 = bias[col + 1]; }
#pragma unroll
            for (int half = 0; half < 2; half++) {
                int row = rowBase + wm * 64 + mt * 16 + lr + half * 8;
                float v0 = acc[mt][nt][half * 2 + 0];
                float v1 = acc[mt][nt][half * 2 + 1];
                if (epi == 1) {
                    v0 = 1.f / (1.f + expf(-(v0 + b0)));
                    v1 = 1.f / (1.f + expf(-(v1 + b1)));
                } else if (epi == 2) {
                    v0 = fmaxf(v0 + b0, 0.f);
                    v1 = fmaxf(v1 + b1, 0.f);
                } else if (epi == 3) {
                    v0 += b0; v1 += b1;
                }
                float2 o; o.x = v0; o.y = v1;
                *(float2*)&Cp[(size_t)row * segN + col] = o;
            }
        }
    }
}

// ============================================================
// Flash attention: one block = (q-tile of 64, b*H+h). 256 threads.
// ============================================================
__device__ __forceinline__ float redmax16(float v) {
    v = fmaxf(v, __shfl_xor_sync(0xffffffffu, v, 8, 16));
    v = fmaxf(v, __shfl_xor_sync(0xffffffffu, v, 4, 16));
    v = fmaxf(v, __shfl_xor_sync(0xffffffffu, v, 2, 16));
    v = fmaxf(v, __shfl_xor_sync(0xffffffffu, v, 1, 16));
    return v;
}
__device__ __forceinline__ float redsum16(float v) {
    v += __shfl_xor_sync(0xffffffffu, v, 8, 16);
    v += __shfl_xor_sync(0xffffffffu, v, 4, 16);
    v += __shfl_xor_sync(0xffffffffu, v, 2, 16);
    v += __shfl_xor_sync(0xffffffffu, v, 1, 16);
    return v;
}

__global__ __launch_bounds__(256) void attn_kernel(
    const float* __restrict__ Q, const float* __restrict__ K,
    const float* __restrict__ V, float* __restrict__ O)
{
    __shared__ float Qs[64][64];
    __shared__ float KP[64][64];   // K transposed then reused as P
    __shared__ float Vs[64][64];

    int tid = threadIdx.x;
    int tx = tid & 15, ty = tid >> 4;
    int qb = blockIdx.x * 64;
    int b = blockIdx.y >> 4, h = blockIdx.y & 15;

    const float* Qb = Q + (size_t)b * Nn * Dd + h * DhC;
    const float* Kb = K + (size_t)b * Nn * Dd + h * DhC;
    const float* Vb = V + (size_t)b * Nn * Dd + h * DhC;

#pragma unroll
    for (int i = 0; i < 4; i++) {
        int e = tid + i * 256;
        int r = e >> 4, c = (e & 15) << 2;
        *(float4*)&Qs[r][c] = *(const float4*)&Qb[(size_t)(qb + r) * Dd + c];
    }

    float m[4], l[4], o[4][4];
#pragma unroll
    for (int i = 0; i < 4; i++) {
        m[i] = -1e30f; l[i] = 0.f;
#pragma unroll
        for (int j = 0; j < 4; j++) o[i][j] = 0.f;
    }

    for (int kt = 0; kt < 16; kt++) {
        __syncthreads();
#pragma unroll
        for (int i = 0; i < 4; i++) {
            int e = tid + i * 256;
            int r = e >> 4, c = (e & 15) << 2;
            float4 kv = *(const float4*)&Kb[(size_t)(kt * 64 + r) * Dd + c];
            KP[c + 0][r] = kv.x; KP[c + 1][r] = kv.y;
            KP[c + 2][r] = kv.z; KP[c + 3][r] = kv.w;
            *(float4*)&Vs[r][c] = *(const float4*)&Vb[(size_t)(kt * 64 + r) * Dd + c];
        }
        __syncthreads();

        float s[4][4];
#pragma unroll
        for (int i = 0; i < 4; i++)
#pragma unroll
            for (int j = 0; j < 4; j++) s[i][j] = 0.f;

#pragma unroll 4
        for (int d = 0; d < 64; d++) {
            float4 k4 = *(float4*)&KP[d][tx << 2];
            float q0 = Qs[(ty << 2) + 0][d];
            float q1 = Qs[(ty << 2) + 1][d];
            float q2 = Qs[(ty << 2) + 2][d];
            float q3 = Qs[(ty << 2) + 3][d];
            s[0][0] += q0 * k4.x; s[0][1] += q0 * k4.y; s[0][2] += q0 * k4.z; s[0][3] += q0 * k4.w;
            s[1][0] += q1 * k4.x; s[1][1] += q1 * k4.y; s[1][2] += q1 * k4.z; s[1][3] += q1 * k4.w;
            s[2][0] += q2 * k4.x; s[2][1] += q2 * k4.y; s[2][2] += q2 * k4.z; s[2][3] += q2 * k4.w;
            s[3][0] += q3 * k4.x; s[3][1] += q3 * k4.y; s[3][2] += q3 * k4.z; s[3][3] += q3 * k4.w;
        }

        const float scale = 0.125f;
#pragma unroll
        for (int i = 0; i < 4; i++) {
#pragma unroll
            for (int j = 0; j < 4; j++) s[i][j] *= scale;
            float tm = fmaxf(fmaxf(s[i][0], s[i][1]), fmaxf(s[i][2], s[i][3]));
            tm = redmax16(tm);
            float mn = fmaxf(m[i], tm);
            float alpha = __expf(m[i] - mn);
            float rs = 0.f;
#pragma unroll
            for (int j = 0; j < 4; j++) { s[i][j] = __expf(s[i][j] - mn); rs += s[i][j]; }
            rs = redsum16(rs);
            l[i] = l[i] * alpha + rs;
            m[i] = mn;
#pragma unroll
            for (int j = 0; j < 4; j++) o[i][j] *= alpha;
        }

        __syncthreads();
#pragma unroll
        for (int i = 0; i < 4; i++) {
            float4 p4; p4.x = s[i][0]; p4.y = s[i][1]; p4.z = s[i][2]; p4.w = s[i][3];
            *(float4*)&KP[(ty << 2) + i][tx << 2] = p4;
        }
        __syncthreads();

#pragma unroll 4
        for (int j = 0; j < 64; j++) {
            float4 v4 = *(float4*)&Vs[j][tx << 2];
            float p0 = KP[(ty << 2) + 0][j];
            float p1 = KP[(ty << 2) + 1][j];
            float p2 = KP[(ty << 2) + 2][j];
            float p3 = KP[(ty << 2) + 3][j];
            o[0][0] += p0 * v4.x; o[0][1] += p0 * v4.y; o[0][2] += p0 * v4.z; o[0][3] += p0 * v4.w;
            o[1][0] += p1 * v4.x; o[1][1] += p1 * v4.y; o[1][2] += p1 * v4.z; o[1][3] += p1 * v4.w;
            o[2][0] += p2 * v4.x; o[2][1] += p2 * v4.y; o[2][2] += p2 * v4.z; o[2][3] += p2 * v4.w;
            o[3][0] += p3 * v4.x; o[3][1] += p3 * v4.y; o[3][2] += p3 * v4.z; o[3][3] += p3 * v4.w;
        }
    }

#pragma unroll
    for (int i = 0; i < 4; i++) {
        float inv = 1.f / l[i];
        float4 r;
        r.x = o[i][0] * inv; r.y = o[i][1] * inv; r.z = o[i][2] * inv; r.w = o[i][3] * inv;
        *(float4*)&O[(size_t)(b * Nn + qb + (ty << 2) + i) * Dd + h * DhC + (tx << 2)] = r;
    }
}

// ============================================================
// Splat influence kernels (unchanged from R1)
// ============================================================
__global__ __launch_bounds__(256) void infl_kernel(
    const float* __restrict__ x, const float* __restrict__ sp,
    const float* __restrict__ sscale, const float* __restrict__ simp,
    float* __restrict__ infl)
{
    __shared__ float xs[Dd];
    __shared__ float red[8];
    int n = blockIdx.x, b = blockIdx.y;
    int tid = threadIdx.x;
    int lane = tid & 31, w = tid >> 5;
    const float* xr = &x[(size_t)(b * Nn + n) * Dd];

    float p2 = 0.f;
    for (int i = tid; i < Dd; i += 256) { float v = xr[i]; xs[i] = v; p2 += v * v; }
#pragma unroll
    for (int off = 16; off; off >>= 1) p2 += __shfl_xor_sync(0xffffffffu, p2, off);
    if (lane == 0) red[w] = p2;
    __syncthreads();
    float x2 = 0.f;
#pragma unroll
    for (int i = 0; i < 8; i++) x2 += red[i];

    for (int s = w; s < Ss; s += 8) {
        const float* spr = &sp[(size_t)s * Dd];
        float dot = 0.f, s2 = 0.f;
        for (int d = lane; d < Dd; d += 32) {
            float pv = spr[d];
            dot += xs[d] * pv;
            s2 += pv * pv;
        }
#pragma unroll
        for (int off = 16; off; off >>= 1) {
            dot += __shfl_xor_sync(0xffffffffu, dot, off);
            s2  += __shfl_xor_sync(0xffffffffu, s2, off);
        }
        if (lane == 0) {
            float d2 = fmaxf(x2 + s2 - 2.f * dot, 0.f);
            float sc = fmaxf(fabsf(sscale[s]), 1e-6f);
            infl[(size_t)(b * Nn + n) * Ss + s] = expf(-0.5f * d2 / (sc * sc)) * fabsf(simp[s]);
        }
    }
}

__global__ __launch_bounds__(256) void total_kernel(
    const float* __restrict__ infl, float* __restrict__ total)
{
    __shared__ float red[8];
    int s = blockIdx.x, b = blockIdx.y, tid = threadIdx.x;
    float acc = 0.f;
    for (int n = tid; n < Nn; n += 256) acc += infl[(size_t)(b * Nn + n) * Ss + s];
#pragma unroll
    for (int off = 16; off; off >>= 1) acc += __shfl_xor_sync(0xffffffffu, acc, off);
    if ((tid & 31) == 0) red[tid >> 5] = acc;
    __syncthreads();
    if (tid == 0) {
        float t = 0.f;
#pragma unroll
        for (int i = 0; i < 8; i++) t += red[i];
        total[b * Ss + s] = fmaxf(t, 1e-8f);
    }
}

__global__ __launch_bounds__(256) void gather_kernel(
    const float* __restrict__ x, const float* __restrict__ infl,
    const float* __restrict__ total, float* __restrict__ gath)
{
    int s = blockIdx.x, b = blockIdx.y, tid = threadIdx.x;
    float acc[4] = {0.f, 0.f, 0.f, 0.f};
    for (int n = 0; n < Nn; n++) {
        float wv = __ldg(&infl[(size_t)(b * Nn + n) * Ss + s]);
        if (wv != 0.f) {
            const float* xr = &x[(size_t)(b * Nn + n) * Dd];
#pragma unroll
            for (int i = 0; i < 4; i++) acc[i] += wv * xr[tid + 256 * i];
        }
    }
    float inv = 1.f / total[b * Ss + s];
#pragma unroll
    for (int i = 0; i < 4; i++)
        gath[(size_t)(b * Ss + s) * Dd + tid + 256 * i] = acc[i] * inv;
}

__global__ __launch_bounds__(128) void trans_kernel(
    const float* __restrict__ enc, const float* __restrict__ Wt,
    const float* __restrict__ bt, float* __restrict__ trans)
{
    int s = blockIdx.x;
    int e = blockIdx.y * 128 + threadIdx.x;
    const float* wp = &Wt[(size_t)s * DbC * DbC];
    const float* e0 = &enc[(size_t)(0 * Ss + s) * DbC];
    const float* e1 = &enc[(size_t)(1 * Ss + s) * DbC];
    float a0 = 0.f, a1 = 0.f;
    for (int d = 0; d < DbC; d++) {
        float wv = wp[(size_t)d * DbC + e];
        a0 += e0[d] * wv;
        a1 += e1[d] * wv;
    }
    float bv = bt[s * DbC + e];
    trans[(size_t)(0 * Ss + s) * DbC + e] = a0 + bv;
    trans[(size_t)(1 * Ss + s) * DbC + e] = a1 + bv;
}

__global__ __launch_bounds__(256) void flow_blend_kernel(
    const float* __restrict__ infl, const float* __restrict__ dec,
    const float* __restrict__ gate, const float* __restrict__ stdo,
    float* __restrict__ blend)
{
    __shared__ float is[Ss];
    int n = blockIdx.x, b = blockIdx.y, tid = threadIdx.x;
    if (tid < Ss) is[tid] = infl[(size_t)(b * Nn + n) * Ss + tid];
    __syncthreads();
#pragma unroll
    for (int i = 0; i < 4; i++) {
        int d = tid + i * 256;
        float acc = 0.f;
#pragma unroll 8
        for (int s = 0; s < Ss; s++)
            acc += is[s] * dec[(size_t)(b * Ss + s) * Dd + d];
        size_t idx = (size_t)(b * Nn + n) * Dd + d;
        blend[idx] = 0.6f * stdo[idx] + 0.4f * acc * gate[idx];
    }
}

// ============================================================
extern "C" void kernel_launch(void* const* d_in, const int* in_sizes, int n_in,
                              void* d_out, int out_size)
{
    const float* x    = (const float*)d_in[0];
    const float* Wq   = (const float*)d_in[1];
    const float* Wk   = (const float*)d_in[2];
    const float* Wv   = (const float*)d_in[3];
    const float* Wo   = (const float*)d_in[4];
    const float* sp   = (const float*)d_in[5];
    const float* ssc  = (const float*)d_in[6];
    const float* simp = (const float*)d_in[7];
    const float* We   = (const float*)d_in[8];
    const float* be   = (const float*)d_in[9];
    const float* Wt   = (const float*)d_in[10];
    const float* bt   = (const float*)d_in[11];
    const float* Wd   = (const float*)d_in[12];
    const float* bd   = (const float*)d_in[13];
    const float* Wg   = (const float*)d_in[14];
    const float* bg   = (const float*)d_in[15];

    float *Qp, *Kp, *Vp, *Gp, *Stdp, *Inflp, *Totp, *Gathp, *Encp, *Transp, *Decp, *Blendp;
    cudaGetSymbolAddress((void**)&Qp, g_Q);
    cudaGetSymbolAddress((void**)&Kp, g_K);
    cudaGetSymbolAddress((void**)&Vp, g_V);
    cudaGetSymbolAddress((void**)&Gp, g_G);
    cudaGetSymbolAddress((void**)&Stdp, g_std);
    cudaGetSymbolAddress((void**)&Inflp, g_infl);
    cudaGetSymbolAddress((void**)&Totp, g_total);
    cudaGetSymbolAddress((void**)&Gathp, g_gath);
    cudaGetSymbolAddress((void**)&Encp, g_enc);
    cudaGetSymbolAddress((void**)&Transp, g_trans);
    cudaGetSymbolAddress((void**)&Decp, g_dec);
    cudaGetSymbolAddress((void**)&Blendp, g_blend);

    const int M = Bb * Nn;   // 2048

    // ---- fused Q/K/V/Gate projection: one GEMM, 4 column segments ----
    {
        GArgs a;
        a.A = x; a.K = Dd; a.segN = Dd;
        a.B[0] = Wq; a.B[1] = Wk; a.B[2] = Wv; a.B[3] = Wg;
        a.bias[0] = nullptr; a.bias[1] = nullptr; a.bias[2] = nullptr; a.bias[3] = bg;
        a.C[0] = Qp; a.C[1] = Kp; a.C[2] = Vp; a.C[3] = Gp;
        a.epi[0] = 0; a.epi[1] = 0; a.epi[2] = 0; a.epi[3] = 1;
        tf32_gemm<<<dim3(32, M / 128), 256>>>(a);
    }

    attn_kernel<<<dim3(Nn / 64, Bb * Hh), 256>>>(Qp, Kp, Vp, Stdp);

    infl_kernel<<<dim3(Nn, Bb), 256>>>(x, sp, ssc, simp, Inflp);
    total_kernel<<<dim3(Ss, Bb), 256>>>(Inflp, Totp);
    gather_kernel<<<dim3(Ss, Bb), 256>>>(x, Inflp, Totp, Gathp);

    // enc = relu(gathered @ We + be): M=128, N=512, K=1024
    {
        GArgs a;
        a.A = Gathp; a.K = Dd; a.segN = DbC;
        for (int i = 0; i < 4; i++) { a.B[i] = We; a.bias[i] = be; a.C[i] = Encp; a.epi[i] = 2; }
        tf32_gemm<<<dim3(DbC / 128, 1), 256>>>(a);
    }

    trans_kernel<<<dim3(Ss, DbC / 128), 128>>>(Encp, Wt, bt, Transp);

    // dec = trans @ Wd + bd: M=128, N=1024, K=512
    {
        GArgs a;
        a.A = Transp; a.K = DbC; a.segN = Dd;
        for (int i = 0; i < 4; i++) { a.B[i] = Wd; a.bias[i] = bd; a.C[i] = Decp; a.epi[i] = 3; }
        tf32_gemm<<<dim3(Dd / 128, 1), 256>>>(a);
    }

    flow_blend_kernel<<<dim3(Nn, Bb), 256>>>(Inflp, Decp, Gp, Stdp, Blendp);

    // final projection: blend @ Wo
    {
        GArgs a;
        a.A = Blendp; a.K = Dd; a.segN = Dd;
        for (int i = 0; i < 4; i++) { a.B[i] = Wo; a.bias[i] = nullptr; a.C[i] = (float*)d_out; a.epi[i] = 0; }
        tf32_gemm<<<dim3(Dd / 128, M / 128), 256>>>(a);
    }
}

// round 4
// speedup vs baseline: 1.6223x; 1.2748x over previous
#include <cuda_runtime.h>
#include <cstdint>

#define Bb 2
#define Nn 1024
#define Dd 1024
#define Hh 16
#define DhC 64
#define Ss 64
#define DbC 512

// -------- scratch (static device globals; no allocations allowed) --------
__device__ float g_Q[Bb*Nn*Dd];
__device__ float g_K[Bb*Nn*Dd];
__device__ float g_V[Bb*Nn*Dd];
__device__ float g_G[Bb*Nn*Dd];      // sigmoid gate
__device__ float g_std[Bb*Nn*Dd];    // std attention out
__device__ float g_infl[Bb*Nn*Ss];
__device__ float g_total[Bb*Ss];
__device__ float g_gath[Bb*Ss*Dd];
__device__ float g_enc[Bb*Ss*DbC];
__device__ float g_trans[Bb*Ss*DbC];
__device__ float g_dec[Bb*Ss*Dd];
__device__ float g_blend[Bb*Nn*Dd];

__device__ __forceinline__ uint32_t f2tf32(float x) {
    uint32_t r;
    asm("cvt.rna.tf32.f32 %0, %1;" : "=r"(r) : "f"(x));
    return r;
}
// exact truncation split: hi keeps top 10 mantissa bits, lo = x - hi exactly
__device__ __forceinline__ float tfhi(float x) {
    return __uint_as_float(__float_as_uint(x) & 0xFFFFE000u);
}

__device__ __forceinline__ void mma_tf32(float* c,
    uint32_t a0, uint32_t a1, uint32_t a2, uint32_t a3,
    uint32_t b0, uint32_t b1)
{
    asm volatile(
        "mma.sync.aligned.m16n8k8.row.col.f32.tf32.tf32.f32 "
        "{%0,%1,%2,%3},{%4,%5,%6,%7},{%8,%9},{%0,%1,%2,%3};"
        : "+f"(c[0]), "+f"(c[1]), "+f"(c[2]), "+f"(c[3])
        : "r"(a0), "r"(a1), "r"(a2), "r"(a3), "r"(b0), "r"(b1));
}

// ============================================================
// TF32 tensor-core GEMM with 3-pass split (unchanged from R3)
// ============================================================
struct GArgs {
    const float* A;
    const float* B[4];
    const float* bias[4];
    float*       C[4];
    int K;
    int segN;
    int epi[4];
};

#define SPAD 140

__global__ __launch_bounds__(256, 2) void tf32_gemm(GArgs g)
{
    __shared__ float As[16][SPAD];
    __shared__ float Bs[16][SPAD];

    const int tid = threadIdx.x;
    const int warp = tid >> 5;
    const int lane = tid & 31;
    const int lr = lane >> 2;
    const int lc = lane & 3;
    const int wm = warp >> 2;
    const int wn = warp & 3;

    const int seg    = (blockIdx.x * 128) / g.segN;
    const int colSeg = (blockIdx.x * 128) % g.segN;
    const int rowBase = blockIdx.y * 128;
    const float* __restrict__ Bp   = g.B[seg];
    const float* __restrict__ bias = g.bias[seg];
    float* __restrict__ Cp         = g.C[seg];
    const int epi  = g.epi[seg];
    const int K    = g.K;
    const int segN = g.segN;

    const int aRow0 = tid >> 2;
    const int aCol0 = (tid & 3) << 2;
    const int bRow0 = tid >> 5;
    const int bCol0 = (tid & 31) << 2;

    float acc[4][4][4];
#pragma unroll
    for (int i = 0; i < 4; i++)
#pragma unroll
        for (int j = 0; j < 4; j++)
#pragma unroll
            for (int q = 0; q < 4; q++) acc[i][j][q] = 0.f;

    const int T = K >> 4;
    float4 sa[2], sb[2];
#pragma unroll
    for (int i = 0; i < 2; i++) {
        sa[i] = *(const float4*)&g.A[(size_t)(rowBase + aRow0 + i * 64) * K + aCol0];
        sb[i] = *(const float4*)&Bp[(size_t)(bRow0 + i * 8) * segN + colSeg + bCol0];
    }

    for (int t = 0; t < T; t++) {
#pragma unroll
        for (int i = 0; i < 2; i++) {
            int r = aRow0 + i * 64;
            As[aCol0 + 0][r] = sa[i].x;
            As[aCol0 + 1][r] = sa[i].y;
            As[aCol0 + 2][r] = sa[i].z;
            As[aCol0 + 3][r] = sa[i].w;
            *(float4*)&Bs[bRow0 + i * 8][bCol0] = sb[i];
        }
        __syncthreads();

        if (t + 1 < T) {
            int k0 = (t + 1) * 16;
#pragma unroll
            for (int i = 0; i < 2; i++) {
                sa[i] = *(const float4*)&g.A[(size_t)(rowBase + aRow0 + i * 64) * K + k0 + aCol0];
                sb[i] = *(const float4*)&Bp[(size_t)(k0 + bRow0 + i * 8) * segN + colSeg + bCol0];
            }
        }

#pragma unroll
        for (int kk = 0; kk < 16; kk += 8) {
            uint32_t bh[4][2], bl[4][2];
#pragma unroll
            for (int nt = 0; nt < 4; nt++) {
                int n0 = wn * 32 + nt * 8 + lr;
                float b0 = Bs[kk + lc][n0];
                float b1 = Bs[kk + 4 + lc][n0];
                bh[nt][0] = f2tf32(b0);
                bl[nt][0] = f2tf32(b0 - __uint_as_float(bh[nt][0]));
                bh[nt][1] = f2tf32(b1);
                bl[nt][1] = f2tf32(b1 - __uint_as_float(bh[nt][1]));
            }
#pragma unroll
            for (int mt = 0; mt < 4; mt++) {
                int m0 = wm * 64 + mt * 16;
                float a0 = As[kk + lc][m0 + lr];
                float a1 = As[kk + lc][m0 + lr + 8];
                float a2 = As[kk + 4 + lc][m0 + lr];
                float a3 = As[kk + 4 + lc][m0 + lr + 8];
                uint32_t ah0 = f2tf32(a0), ah1 = f2tf32(a1), ah2 = f2tf32(a2), ah3 = f2tf32(a3);
                uint32_t al0 = f2tf32(a0 - __uint_as_float(ah0));
                uint32_t al1 = f2tf32(a1 - __uint_as_float(ah1));
                uint32_t al2 = f2tf32(a2 - __uint_as_float(ah2));
                uint32_t al3 = f2tf32(a3 - __uint_as_float(ah3));
#pragma unroll
                for (int nt = 0; nt < 4; nt++) {
                    mma_tf32(acc[mt][nt], ah0, ah1, ah2, ah3, bh[nt][0], bh[nt][1]);
                    mma_tf32(acc[mt][nt], ah0, ah1, ah2, ah3, bl[nt][0], bl[nt][1]);
                    mma_tf32(acc[mt][nt], al0, al1, al2, al3, bh[nt][0], bh[nt][1]);
                }
            }
        }
        __syncthreads();
    }

#pragma unroll
    for (int mt = 0; mt < 4; mt++) {
#pragma unroll
        for (int nt = 0; nt < 4; nt++) {
            int col = colSeg + wn * 32 + nt * 8 + 2 * lc;
            float b0 = 0.f, b1 = 0.f;
            if (epi != 0) { b0 = bias[col]; b1 = bias[col + 1]; }
#pragma unroll
            for (int half = 0; half < 2; half++) {
                int row = rowBase + wm * 64 + mt * 16 + lr + half * 8;
                float v0 = acc[mt][nt][half * 2 + 0];
                float v1 = acc[mt][nt][half * 2 + 1];
                if (epi == 1) {
                    v0 = 1.f / (1.f + expf(-(v0 + b0)));
                    v1 = 1.f / (1.f + expf(-(v1 + b1)));
                } else if (epi == 2) {
                    v0 = fmaxf(v0 + b0, 0.f);
                    v1 = fmaxf(v1 + b1, 0.f);
                } else if (epi == 3) {
                    v0 += b0; v1 += b1;
                }
                float2 o; o.x = v0; o.y = v1;
                *(float2*)&Cp[(size_t)row * segN + col] = o;
            }
        }
    }
}

// ============================================================
// Tensor-core flash attention (tf32 3-pass split).
// Block: 256 thr / 8 warps; q-tile 128 (16 rows per warp);
// grid (Nn/128, B*H). Softmax warp-local. K pad 68, V pad 72
// (both STS and fragment-LDS conflict-free).
// ============================================================
__global__ __launch_bounds__(256, 1) void attn_mma_kernel(
    const float* __restrict__ Q, const float* __restrict__ K,
    const float* __restrict__ V, float* __restrict__ O)
{
    __shared__ float Ks[64][68];
    __shared__ float Vs[64][72];

    const int tid = threadIdx.x;
    const int warp = tid >> 5;
    const int lane = tid & 31;
    const int g = lane >> 2;     // row group 0..7
    const int t = lane & 3;      // thread in group

    const int qb = blockIdx.x * 128;
    const int b = blockIdx.y >> 4, h = blockIdx.y & 15;
    const float* Qb = Q + (size_t)b * Nn * Dd + h * DhC;
    const float* Kb = K + (size_t)b * Nn * Dd + h * DhC;
    const float* Vb = V + (size_t)b * Nn * Dd + h * DhC;

    // ---- Q fragments: pre-scaled by Dh^-0.5, split hi/lo, kept in regs ----
    const int r0 = qb + warp * 16 + g;
    uint32_t qh[8][4];
    float    ql[8][4];
#pragma unroll
    for (int c = 0; c < 8; c++) {
        float v0 = Qb[(size_t)r0 * Dd + 8 * c + t] * 0.125f;
        float v1 = Qb[(size_t)(r0 + 8) * Dd + 8 * c + t] * 0.125f;
        float v2 = Qb[(size_t)r0 * Dd + 8 * c + t + 4] * 0.125f;
        float v3 = Qb[(size_t)(r0 + 8) * Dd + 8 * c + t + 4] * 0.125f;
        float h0 = tfhi(v0), h1 = tfhi(v1), h2 = tfhi(v2), h3 = tfhi(v3);
        qh[c][0] = __float_as_uint(h0); ql[c][0] = v0 - h0;
        qh[c][1] = __float_as_uint(h1); ql[c][1] = v1 - h1;
        qh[c][2] = __float_as_uint(h2); ql[c][2] = v2 - h2;
        qh[c][3] = __float_as_uint(h3); ql[c][3] = v3 - h3;
    }

    float m0 = -1e30f, m1 = -1e30f, l0 = 0.f, l1 = 0.f;
    float o[8][4];
#pragma unroll
    for (int j = 0; j < 8; j++)
#pragma unroll
        for (int q = 0; q < 4; q++) o[j][q] = 0.f;

    // prefetch tile 0
    float4 kreg[4], vreg[4];
#pragma unroll
    for (int i = 0; i < 4; i++) {
        int f = tid + i * 256;
        int r = f >> 4, c4 = (f & 15) << 2;
        kreg[i] = *(const float4*)&Kb[(size_t)r * Dd + c4];
        vreg[i] = *(const float4*)&Vb[(size_t)r * Dd + c4];
    }

    const int src_lo = (lane & ~3) | (t >> 1);
    const int src_hi = src_lo + 2;
    const bool odd = (t & 1);

    for (int kt = 0; kt < 16; kt++) {
        __syncthreads();
#pragma unroll
        for (int i = 0; i < 4; i++) {
            int f = tid + i * 256;
            int r = f >> 4, c4 = (f & 15) << 2;
            *(float4*)&Ks[r][c4] = kreg[i];
            *(float4*)&Vs[r][c4] = vreg[i];
        }
        __syncthreads();

        if (kt < 15) {
#pragma unroll
            for (int i = 0; i < 4; i++) {
                int f = tid + i * 256;
                int r = f >> 4, c4 = (f & 15) << 2;
                kreg[i] = *(const float4*)&Kb[(size_t)((kt + 1) * 64 + r) * Dd + c4];
                vreg[i] = *(const float4*)&Vb[(size_t)((kt + 1) * 64 + r) * Dd + c4];
            }
        }

        // ---- S = Q @ K^T (pre-scaled) ----
        float s[8][4];
#pragma unroll
        for (int j = 0; j < 8; j++)
#pragma unroll
            for (int q = 0; q < 4; q++) s[j][q] = 0.f;

#pragma unroll
        for (int c = 0; c < 8; c++) {
#pragma unroll
            for (int j = 0; j < 8; j++) {
                float b0 = Ks[8 * j + g][8 * c + t];
                float b1 = Ks[8 * j + g][8 * c + t + 4];
                float bh0 = tfhi(b0), bh1 = tfhi(b1);
                uint32_t ubh0 = __float_as_uint(bh0), ubh1 = __float_as_uint(bh1);
                uint32_t ubl0 = __float_as_uint(b0 - bh0), ubl1 = __float_as_uint(b1 - bh1);
                mma_tf32(s[j], qh[c][0], qh[c][1], qh[c][2], qh[c][3], ubh0, ubh1);
                mma_tf32(s[j], qh[c][0], qh[c][1], qh[c][2], qh[c][3], ubl0, ubl1);
                mma_tf32(s[j], __float_as_uint(ql[c][0]), __float_as_uint(ql[c][1]),
                               __float_as_uint(ql[c][2]), __float_as_uint(ql[c][3]), ubh0, ubh1);
            }
        }

        // ---- online softmax (warp-local rows) ----
        float mx0 = -1e30f, mx1 = -1e30f;
#pragma unroll
        for (int j = 0; j < 8; j++) {
            mx0 = fmaxf(mx0, fmaxf(s[j][0], s[j][1]));
            mx1 = fmaxf(mx1, fmaxf(s[j][2], s[j][3]));
        }
        mx0 = fmaxf(mx0, __shfl_xor_sync(0xffffffffu, mx0, 1));
        mx0 = fmaxf(mx0, __shfl_xor_sync(0xffffffffu, mx0, 2));
        mx1 = fmaxf(mx1, __shfl_xor_sync(0xffffffffu, mx1, 1));
        mx1 = fmaxf(mx1, __shfl_xor_sync(0xffffffffu, mx1, 2));
        float mn0 = fmaxf(m0, mx0), mn1 = fmaxf(m1, mx1);
        float al0 = __expf(m0 - mn0), al1 = __expf(m1 - mn1);
        m0 = mn0; m1 = mn1;
        float rs0 = 0.f, rs1 = 0.f;
#pragma unroll
        for (int j = 0; j < 8; j++) {
            s[j][0] = __expf(s[j][0] - mn0); rs0 += s[j][0];
            s[j][1] = __expf(s[j][1] - mn0); rs0 += s[j][1];
            s[j][2] = __expf(s[j][2] - mn1); rs1 += s[j][2];
            s[j][3] = __expf(s[j][3] - mn1); rs1 += s[j][3];
        }
        l0 = l0 * al0 + rs0;
        l1 = l1 * al1 + rs1;
#pragma unroll
        for (int j = 0; j < 8; j++) {
            o[j][0] *= al0; o[j][1] *= al0; o[j][2] *= al1; o[j][3] *= al1;
        }

        // ---- O += P @ V  (P rearranged C-frag -> A-frag via shuffles) ----
#pragma unroll
        for (int c = 0; c < 8; c++) {
            float e00 = __shfl_sync(0xffffffffu, s[c][0], src_lo);
            float e01 = __shfl_sync(0xffffffffu, s[c][1], src_lo);
            float e20 = __shfl_sync(0xffffffffu, s[c][2], src_lo);
            float e21 = __shfl_sync(0xffffffffu, s[c][3], src_lo);
            float f00 = __shfl_sync(0xffffffffu, s[c][0], src_hi);
            float f01 = __shfl_sync(0xffffffffu, s[c][1], src_hi);
            float f20 = __shfl_sync(0xffffffffu, s[c][2], src_hi);
            float f21 = __shfl_sync(0xffffffffu, s[c][3], src_hi);
            float a0 = odd ? e01 : e00;
            float a1 = odd ? e21 : e20;
            float a2 = odd ? f01 : f00;
            float a3 = odd ? f21 : f20;
            float ah0 = tfhi(a0), ah1 = tfhi(a1), ah2 = tfhi(a2), ah3 = tfhi(a3);
            uint32_t uah0 = __float_as_uint(ah0), uah1 = __float_as_uint(ah1);
            uint32_t uah2 = __float_as_uint(ah2), uah3 = __float_as_uint(ah3);
            uint32_t ual0 = __float_as_uint(a0 - ah0), ual1 = __float_as_uint(a1 - ah1);
            uint32_t ual2 = __float_as_uint(a2 - ah2), ual3 = __float_as_uint(a3 - ah3);
#pragma unroll
            for (int j = 0; j < 8; j++) {
                float b0 = Vs[8 * c + t][8 * j + g];
                float b1 = Vs[8 * c + t + 4][8 * j + g];
                float bh0 = tfhi(b0), bh1 = tfhi(b1);
                uint32_t ubh0 = __float_as_uint(bh0), ubh1 = __float_as_uint(bh1);
                uint32_t ubl0 = __float_as_uint(b0 - bh0), ubl1 = __float_as_uint(b1 - bh1);
                mma_tf32(o[j], uah0, uah1, uah2, uah3, ubh0, ubh1);
                mma_tf32(o[j], uah0, uah1, uah2, uah3, ubl0, ubl1);
                mma_tf32(o[j], ual0, ual1, ual2, ual3, ubh0, ubh1);
            }
        }
    }

    // ---- finalize: sum l across the 4 lanes of each row group, write O ----
    l0 += __shfl_xor_sync(0xffffffffu, l0, 1);
    l0 += __shfl_xor_sync(0xffffffffu, l0, 2);
    l1 += __shfl_xor_sync(0xffffffffu, l1, 1);
    l1 += __shfl_xor_sync(0xffffffffu, l1, 2);
    float inv0 = 1.f / l0, inv1 = 1.f / l1;
#pragma unroll
    for (int j = 0; j < 8; j++) {
        int col = h * DhC + 8 * j + 2 * t;
        float2 w0; w0.x = o[j][0] * inv0; w0.y = o[j][1] * inv0;
        float2 w1; w1.x = o[j][2] * inv1; w1.y = o[j][3] * inv1;
        *(float2*)&O[(size_t)(b * Nn + r0) * Dd + col] = w0;
        *(float2*)&O[(size_t)(b * Nn + r0 + 8) * Dd + col] = w1;
    }
}

// ============================================================
// Splat pipeline kernels (unchanged)
// ============================================================
__global__ __launch_bounds__(256) void infl_kernel(
    const float* __restrict__ x, const float* __restrict__ sp,
    const float* __restrict__ sscale, const float* __restrict__ simp,
    float* __restrict__ infl)
{
    __shared__ float xs[Dd];
    __shared__ float red[8];
    int n = blockIdx.x, b = blockIdx.y;
    int tid = threadIdx.x;
    int lane = tid & 31, w = tid >> 5;
    const float* xr = &x[(size_t)(b * Nn + n) * Dd];

    float p2 = 0.f;
    for (int i = tid; i < Dd; i += 256) { float v = xr[i]; xs[i] = v; p2 += v * v; }
#pragma unroll
    for (int off = 16; off; off >>= 1) p2 += __shfl_xor_sync(0xffffffffu, p2, off);
    if (lane == 0) red[w] = p2;
    __syncthreads();
    float x2 = 0.f;
#pragma unroll
    for (int i = 0; i < 8; i++) x2 += red[i];

    for (int s = w; s < Ss; s += 8) {
        const float* spr = &sp[(size_t)s * Dd];
        float dot = 0.f, s2 = 0.f;
        for (int d = lane; d < Dd; d += 32) {
            float pv = spr[d];
            dot += xs[d] * pv;
            s2 += pv * pv;
        }
#pragma unroll
        for (int off = 16; off; off >>= 1) {
            dot += __shfl_xor_sync(0xffffffffu, dot, off);
            s2  += __shfl_xor_sync(0xffffffffu, s2, off);
        }
        if (lane == 0) {
            float d2 = fmaxf(x2 + s2 - 2.f * dot, 0.f);
            float sc = fmaxf(fabsf(sscale[s]), 1e-6f);
            infl[(size_t)(b * Nn + n) * Ss + s] = expf(-0.5f * d2 / (sc * sc)) * fabsf(simp[s]);
        }
    }
}

__global__ __launch_bounds__(256) void total_kernel(
    const float* __restrict__ infl, float* __restrict__ total)
{
    __shared__ float red[8];
    int s = blockIdx.x, b = blockIdx.y, tid = threadIdx.x;
    float acc = 0.f;
    for (int n = tid; n < Nn; n += 256) acc += infl[(size_t)(b * Nn + n) * Ss + s];
#pragma unroll
    for (int off = 16; off; off >>= 1) acc += __shfl_xor_sync(0xffffffffu, acc, off);
    if ((tid & 31) == 0) red[tid >> 5] = acc;
    __syncthreads();
    if (tid == 0) {
        float t = 0.f;
#pragma unroll
        for (int i = 0; i < 8; i++) t += red[i];
        total[b * Ss + s] = fmaxf(t, 1e-8f);
    }
}

__global__ __launch_bounds__(256) void gather_kernel(
    const float* __restrict__ x, const float* __restrict__ infl,
    const float* __restrict__ total, float* __restrict__ gath)
{
    int s = blockIdx.x, b = blockIdx.y, tid = threadIdx.x;
    float acc[4] = {0.f, 0.f, 0.f, 0.f};
    for (int n = 0; n < Nn; n++) {
        float wv = __ldg(&infl[(size_t)(b * Nn + n) * Ss + s]);
        if (wv != 0.f) {
            const float* xr = &x[(size_t)(b * Nn + n) * Dd];
#pragma unroll
            for (int i = 0; i < 4; i++) acc[i] += wv * xr[tid + 256 * i];
        }
    }
    float inv = 1.f / total[b * Ss + s];
#pragma unroll
    for (int i = 0; i < 4; i++)
        gath[(size_t)(b * Ss + s) * Dd + tid + 256 * i] = acc[i] * inv;
}

__global__ __launch_bounds__(128) void trans_kernel(
    const float* __restrict__ enc, const float* __restrict__ Wt,
    const float* __restrict__ bt, float* __restrict__ trans)
{
    int s = blockIdx.x;
    int e = blockIdx.y * 128 + threadIdx.x;
    const float* wp = &Wt[(size_t)s * DbC * DbC];
    const float* e0 = &enc[(size_t)(0 * Ss + s) * DbC];
    const float* e1 = &enc[(size_t)(1 * Ss + s) * DbC];
    float a0 = 0.f, a1 = 0.f;
    for (int d = 0; d < DbC; d++) {
        float wv = wp[(size_t)d * DbC + e];
        a0 += e0[d] * wv;
        a1 += e1[d] * wv;
    }
    float bv = bt[s * DbC + e];
    trans[(size_t)(0 * Ss + s) * DbC + e] = a0 + bv;
    trans[(size_t)(1 * Ss + s) * DbC + e] = a1 + bv;
}

__global__ __launch_bounds__(256) void flow_blend_kernel(
    const float* __restrict__ infl, const float* __restrict__ dec,
    const float* __restrict__ gate, const float* __restrict__ stdo,
    float* __restrict__ blend)
{
    __shared__ float is[Ss];
    int n = blockIdx.x, b = blockIdx.y, tid = threadIdx.x;
    if (tid < Ss) is[tid] = infl[(size_t)(b * Nn + n) * Ss + tid];
    __syncthreads();
#pragma unroll
    for (int i = 0; i < 4; i++) {
        int d = tid + i * 256;
        float acc = 0.f;
#pragma unroll 8
        for (int s = 0; s < Ss; s++)
            acc += is[s] * dec[(size_t)(b * Ss + s) * Dd + d];
        size_t idx = (size_t)(b * Nn + n) * Dd + d;
        blend[idx] = 0.6f * stdo[idx] + 0.4f * acc * gate[idx];
    }
}

// ============================================================
extern "C" void kernel_launch(void* const* d_in, const int* in_sizes, int n_in,
                              void* d_out, int out_size)
{
    const float* x    = (const float*)d_in[0];
    const float* Wq   = (const float*)d_in[1];
    const float* Wk   = (const float*)d_in[2];
    const float* Wv   = (const float*)d_in[3];
    const float* Wo   = (const float*)d_in[4];
    const float* sp   = (const float*)d_in[5];
    const float* ssc  = (const float*)d_in[6];
    const float* simp = (const float*)d_in[7];
    const float* We   = (const float*)d_in[8];
    const float* be   = (const float*)d_in[9];
    const float* Wt   = (const float*)d_in[10];
    const float* bt   = (const float*)d_in[11];
    const float* Wd   = (const float*)d_in[12];
    const float* bd   = (const float*)d_in[13];
    const float* Wg   = (const float*)d_in[14];
    const float* bg   = (const float*)d_in[15];

    float *Qp, *Kp, *Vp, *Gp, *Stdp, *Inflp, *Totp, *Gathp, *Encp, *Transp, *Decp, *Blendp;
    cudaGetSymbolAddress((void**)&Qp, g_Q);
    cudaGetSymbolAddress((void**)&Kp, g_K);
    cudaGetSymbolAddress((void**)&Vp, g_V);
    cudaGetSymbolAddress((void**)&Gp, g_G);
    cudaGetSymbolAddress((void**)&Stdp, g_std);
    cudaGetSymbolAddress((void**)&Inflp, g_infl);
    cudaGetSymbolAddress((void**)&Totp, g_total);
    cudaGetSymbolAddress((void**)&Gathp, g_gath);
    cudaGetSymbolAddress((void**)&Encp, g_enc);
    cudaGetSymbolAddress((void**)&Transp, g_trans);
    cudaGetSymbolAddress((void**)&Decp, g_dec);
    cudaGetSymbolAddress((void**)&Blendp, g_blend);

    const int M = Bb * Nn;   // 2048

    // ---- fused Q/K/V/Gate projection ----
    {
        GArgs a;
        a.A = x; a.K = Dd; a.segN = Dd;
        a.B[0] = Wq; a.B[1] = Wk; a.B[2] = Wv; a.B[3] = Wg;
        a.bias[0] = nullptr; a.bias[1] = nullptr; a.bias[2] = nullptr; a.bias[3] = bg;
        a.C[0] = Qp; a.C[1] = Kp; a.C[2] = Vp; a.C[3] = Gp;
        a.epi[0] = 0; a.epi[1] = 0; a.epi[2] = 0; a.epi[3] = 1;
        tf32_gemm<<<dim3(32, M / 128), 256>>>(a);
    }

    attn_mma_kernel<<<dim3(Nn / 128, Bb * Hh), 256>>>(Qp, Kp, Vp, Stdp);

    infl_kernel<<<dim3(Nn, Bb), 256>>>(x, sp, ssc, simp, Inflp);
    total_kernel<<<dim3(Ss, Bb), 256>>>(Inflp, Totp);
    gather_kernel<<<dim3(Ss, Bb), 256>>>(x, Inflp, Totp, Gathp);

    {
        GArgs a;
        a.A = Gathp; a.K = Dd; a.segN = DbC;
        for (int i = 0; i < 4; i++) { a.B[i] = We; a.bias[i] = be; a.C[i] = Encp; a.epi[i] = 2; }
        tf32_gemm<<<dim3(DbC / 128, 1), 256>>>(a);
    }

    trans_kernel<<<dim3(Ss, DbC / 128), 128>>>(Encp, Wt, bt, Transp);

    {
        GArgs a;
        a.A = Transp; a.K = DbC; a.segN = Dd;
        for (int i = 0; i < 4; i++) { a.B[i] = Wd; a.bias[i] = bd; a.C[i] = Decp; a.epi[i] = 3; }
        tf32_gemm<<<dim3(Dd / 128, 1), 256>>>(a);
    }

    flow_blend_kernel<<<dim3(Nn, Bb), 256>>>(Inflp, Decp, Gp, Stdp, Blendp);

    {
        GArgs a;
        a.A = Blendp; a.K = Dd; a.segN = Dd;
        for (int i = 0; i < 4; i++) { a.B[i] = Wo; a.bias[i] = nullptr; a.C[i] = (float*)d_out; a.epi[i] = 0; }
        tf32_gemm<<<dim3(Dd / 128, M / 128), 256>>>(a);
    }
}